// round 3
// baseline (speedup 1.0000x reference)
#include <cuda_runtime.h>
#include <math.h>

#define NCH 8            // 2 batches x 4 classes
#define GD 96            // input spatial dim
#define PD 48            // pooled dim
#define PVOL (PD*PD*PD)  // 110592
#define ND 46            // base-voxel dim (48 - 2)
#define HALF_D 27
#define GSZ 64           // padded gram size (54 data rows + ones row at 54)

#define BY 6
#define BZ 6
#define RXP 50           // padded raw tile x-extent (48 used, 50 for bank decorrelation)
#define RY 8             // BY + 2
#define RZ 8             // BZ + 2
#define TILE (RZ*RY*RXP) // 3200 floats per sub-tile

static __device__ float  g_la[NCH*PVOL];
static __device__ float  g_pr[NCH*PVOL];
static __device__ double g_gram[NCH*GSZ*GSZ];

// ---------------------------------------------------------------------------
__global__ void zero_kernel(float* out) {
    int i = blockIdx.x * blockDim.x + threadIdx.x;
    if (i < NCH*GSZ*GSZ) g_gram[i] = 0.0;
    if (i == 0) out[0] = 0.0f;
}

// ---------------------------------------------------------------------------
// Pool: sigmoid+mask and one-hot, 2x2x2 max-pool. One thread per pooled voxel
// per channel. Labels arrive as int32 (harness converts int64 -> int32).
__global__ void pool_kernel(const float* __restrict__ logits,
                            const int* __restrict__ labels) {
    int idx = blockIdx.x * blockDim.x + threadIdx.x;
    if (idx >= NCH*PVOL) return;
    int ch  = idx / PVOL;
    int rem = idx - ch * PVOL;
    int p0 = rem / (PD*PD);
    int p1 = (rem / PD) % PD;
    int p2 = rem % PD;
    int n = ch >> 2;
    int c = ch & 3;

    const float* lg = logits + (size_t)ch * GD*GD*GD;
    const int*   lb = labels + (size_t)n  * GD*GD*GD;

    float la = 0.f, pr = 0.f;
    #pragma unroll
    for (int d0 = 0; d0 < 2; d0++) {
        #pragma unroll
        for (int d1 = 0; d1 < 2; d1++) {
            int base = ((2*p0 + d0) * GD + (2*p1 + d1)) * GD + 2*p2;
            float2 lv = *reinterpret_cast<const float2*>(lg + base);
            int2   bv = *reinterpret_cast<const int2*>(lb + base);
            // element 0
            {
                bool m = (bv.x < 4);
                if (m && bv.x == c) la = 1.f;
                float s = 1.f / (1.f + expf(-lv.x));
                float p = (m ? s : 0.f) + 1e-6f;
                pr = fmaxf(pr, p);
            }
            // element 1
            {
                bool m = (bv.y < 4);
                if (m && bv.y == c) la = 1.f;
                float s = 1.f / (1.f + expf(-lv.y));
                float p = (m ? s : 0.f) + 1e-6f;
                pr = fmaxf(pr, p);
            }
        }
    }
    g_la[idx] = la;
    g_pr[idx] = pr;
}

// ---------------------------------------------------------------------------
// Gram: per channel, X * X^T over M = 46^3 base voxels where X rows are the
// 27 shifted la copies, 27 shifted pr copies, and a constant-1 row (row 54,
// giving the sums needed for mean-correction for free).
// Block = 64 threads (8x8 grid), each thread owns an 8x8 register tile of the
// 64x64 (padded) Gram. K-loop walks base voxels of a smem raw tile.
__device__ __forceinline__ int delta_of(int r) {
    if (r < 27)  return ((r/9)*RY + (r/3)%3) * RXP + (r%3);
    if (r < 54) { int q = r - 27; return TILE + ((q/9)*RY + (q/3)%3) * RXP + (q%3); }
    return 2*TILE;   // ones tile (rows >= 54 read constant 1.0; rows > 54 unused)
}

__global__ __launch_bounds__(64) void gram_kernel() {
    __shared__ float s[3*TILE];
    int ch = blockIdx.z;
    int y0 = blockIdx.x * BY;
    int z0 = blockIdx.y * BZ;
    int tid = threadIdx.x;

    const float* la = g_la + (size_t)ch * PVOL;
    const float* pr = g_pr + (size_t)ch * PVOL;

    // cooperative load of raw tiles (with halo), plus ones tile
    for (int i = tid; i < TILE; i += 64) {
        int x = i % RXP;
        int t = i / RXP;
        int y = t % RY;
        int z = t / RY;
        int gy = y0 + y, gz = z0 + z;
        float va = 0.f, vb = 0.f;
        if (x < PD && gy < PD && gz < PD) {
            int gi = (gz*PD + gy)*PD + x;
            va = la[gi];
            vb = pr[gi];
        }
        s[i]          = va;
        s[TILE + i]   = vb;
        s[2*TILE + i] = 1.f;
    }
    __syncthreads();

    int ty = tid >> 3, tx = tid & 7;
    int rdel[8], cdel[8];
    #pragma unroll
    for (int i = 0; i < 8; i++) {
        rdel[i] = delta_of(ty*8 + i);
        cdel[i] = delta_of(tx*8 + i);
    }

    float acc[8][8];
    #pragma unroll
    for (int i = 0; i < 8; i++)
        #pragma unroll
        for (int j = 0; j < 8; j++) acc[i][j] = 0.f;

    int yC = min(BY, ND - y0);
    int zC = min(BZ, ND - z0);

    for (int zb = 0; zb < zC; zb++) {
        for (int yb = 0; yb < yC; yb++) {
            int kb = (zb*RY + yb) * RXP;
            #pragma unroll 2
            for (int xb = 0; xb < ND; xb++) {
                int k = kb + xb;
                float a[8], b[8];
                #pragma unroll
                for (int i = 0; i < 8; i++) a[i] = s[rdel[i] + k];
                #pragma unroll
                for (int j = 0; j < 8; j++) b[j] = s[cdel[j] + k];
                #pragma unroll
                for (int i = 0; i < 8; i++)
                    #pragma unroll
                    for (int j = 0; j < 8; j++)
                        acc[i][j] = fmaf(a[i], b[j], acc[i][j]);
            }
        }
    }

    double* G = g_gram + (size_t)ch * GSZ * GSZ;
    #pragma unroll
    for (int i = 0; i < 8; i++) {
        int r = ty*8 + i;
        if (r > 54) continue;
        #pragma unroll
        for (int j = 0; j < 8; j++) {
            int c = tx*8 + j;
            if (c > 54) continue;
            atomicAdd(&G[r*GSZ + c], (double)acc[i][j]);
        }
    }
}

// ---------------------------------------------------------------------------
// Finalize: per channel (8 blocks, 32 threads): mean-correct Gram into
// la_cov / pr_cov / la_pr, Cholesky-solve, approx-var Cholesky, sum log diag.
__device__ void chol27(double* A, int tid) {
    for (int k = 0; k < 27; k++) {
        if (tid == 0) A[k*27 + k] = sqrt(A[k*27 + k]);
        __syncthreads();
        double dk = A[k*27 + k];
        for (int i = k + 1 + tid; i < 27; i += 32) A[i*27 + k] /= dk;
        __syncthreads();
        for (int i = k + 1 + tid; i < 27; i += 32) {
            double lik = A[i*27 + k];
            for (int j = k + 1; j <= i; j++) A[i*27 + j] -= lik * A[j*27 + k];
        }
        __syncthreads();
    }
}

__global__ void finalize_kernel(float* out) {
    __shared__ double Cla[27*27], P[27*27], X[27*27], T[27*27];
    int ch = blockIdx.x;
    int tid = threadIdx.x;
    const double* G = g_gram + (size_t)ch * GSZ * GSZ;
    const double M = (double)(ND*ND*ND);   // 97336
    const double ALPHA = 0.0005;

    for (int e = tid; e < 27*27; e += 32) {
        int i = e / 27, j = e % 27;
        double Sli = G[i*GSZ + 54];          // sum of la row i
        double Spj = G[(27+j)*GSZ + 54];     // sum of pr row j
        double Slj = G[j*GSZ + 54];
        double Spi = G[(27+i)*GSZ + 54];
        Cla[e] = G[i*GSZ + j]             - Sli*Slj / M;
        P[e]   = G[(27+i)*GSZ + (27+j)]   - Spi*Spj / M + (i == j ? ALPHA : 0.0);
        X[e]   = G[i*GSZ + (27+j)]        - Sli*Spj / M;
    }
    __syncthreads();

    chol27(P, tid);   // P = Lp (lower), Lp Lp^T = pr_cov + aI

    // T = Lp^{-1} X^T : one RHS column per thread
    if (tid < 27) {
        int m = tid;
        double t[27];
        for (int i = 0; i < 27; i++) {
            double v = X[m*27 + i];
            for (int j = 0; j < i; j++) v -= P[i*27 + j] * t[j];
            t[i] = v / P[i*27 + i];
        }
        for (int i = 0; i < 27; i++) T[i*27 + m] = t[i];
    }
    __syncthreads();

    // appro = la_cov - T^T T + aI  (reuse P)
    for (int e = tid; e < 27*27; e += 32) {
        int i = e / 27, j = e % 27;
        double v = Cla[e];
        for (int k = 0; k < 27; k++) v -= T[k*27 + i] * T[k*27 + j];
        P[e] = v + (i == j ? ALPHA : 0.0);
    }
    __syncthreads();

    chol27(P, tid);

    if (tid == 0) {
        double rmi = 0.0;
        for (int k = 0; k < 27; k++) rmi += log(P[k*27 + k] + 1e-8);
        // sum_c mean_n rmi / 27  ==  sum_ch rmi_ch / 54
        atomicAdd(out, (float)(rmi / 54.0));
    }
}

// ---------------------------------------------------------------------------
extern "C" void kernel_launch(void* const* d_in, const int* in_sizes, int n_in,
                              void* d_out, int out_size) {
    const float* logits = (const float*)d_in[0];
    const int*   labels = (const int*)d_in[1];
    float* out = (float*)d_out;

    zero_kernel<<<(NCH*GSZ*GSZ + 255)/256, 256>>>(out);
    pool_kernel<<<(NCH*PVOL + 255)/256, 256>>>(logits, labels);
    dim3 g((ND + BY - 1)/BY, (ND + BZ - 1)/BZ, NCH);   // (8, 8, 8)
    gram_kernel<<<g, 64>>>();
    finalize_kernel<<<NCH, 32>>>(out);
}

// round 4
// speedup vs baseline: 1.3601x; 1.3601x over previous
#include <cuda_runtime.h>
#include <math.h>

#define NCH 8            // 2 batches x 4 classes
#define GD 96            // input spatial dim
#define PD 48            // pooled dim
#define PVOL (PD*PD*PD)  // 110592
#define ND 46            // base-voxel dim (48 - 2)
#define HALF_D 27
#define GSZ 64           // padded gram size (54 data rows + ones row at 54)

#define BY 6
#define BZ 6
#define RXP 50           // padded raw tile x-extent
#define RY 8             // BY + 2
#define RZ 8             // BZ + 2
#define TILE (RZ*RY*RXP) // 3200 floats per sub-tile

#define FT 128           // finalize threads

static __device__ float  g_la[NCH*PVOL];
static __device__ float  g_pr[NCH*PVOL];
static __device__ double g_gram[NCH*GSZ*GSZ];

// ---------------------------------------------------------------------------
__global__ void zero_kernel(float* out) {
    int i = blockIdx.x * blockDim.x + threadIdx.x;
    if (i < NCH*GSZ*GSZ) g_gram[i] = 0.0;
    if (i == 0) out[0] = 0.0f;
}

// ---------------------------------------------------------------------------
__global__ void pool_kernel(const float* __restrict__ logits,
                            const int* __restrict__ labels) {
    int idx = blockIdx.x * blockDim.x + threadIdx.x;
    if (idx >= NCH*PVOL) return;
    int ch  = idx / PVOL;
    int rem = idx - ch * PVOL;
    int p0 = rem / (PD*PD);
    int p1 = (rem / PD) % PD;
    int p2 = rem % PD;
    int n = ch >> 2;
    int c = ch & 3;

    const float* lg = logits + (size_t)ch * GD*GD*GD;
    const int*   lb = labels + (size_t)n  * GD*GD*GD;

    float la = 0.f, pr = 0.f;
    #pragma unroll
    for (int d0 = 0; d0 < 2; d0++) {
        #pragma unroll
        for (int d1 = 0; d1 < 2; d1++) {
            int base = ((2*p0 + d0) * GD + (2*p1 + d1)) * GD + 2*p2;
            float2 lv = *reinterpret_cast<const float2*>(lg + base);
            int2   bv = *reinterpret_cast<const int2*>(lb + base);
            {
                bool m = (bv.x < 4);
                if (m && bv.x == c) la = 1.f;
                float s = 1.f / (1.f + expf(-lv.x));
                float p = (m ? s : 0.f) + 1e-6f;
                pr = fmaxf(pr, p);
            }
            {
                bool m = (bv.y < 4);
                if (m && bv.y == c) la = 1.f;
                float s = 1.f / (1.f + expf(-lv.y));
                float p = (m ? s : 0.f) + 1e-6f;
                pr = fmaxf(pr, p);
            }
        }
    }
    g_la[idx] = la;
    g_pr[idx] = pr;
}

// ---------------------------------------------------------------------------
__device__ __forceinline__ int delta_of(int r) {
    if (r < 27)  return ((r/9)*RY + (r/3)%3) * RXP + (r%3);
    if (r < 54) { int q = r - 27; return TILE + ((q/9)*RY + (q/3)%3) * RXP + (q%3); }
    return 2*TILE;
}

__global__ __launch_bounds__(64) void gram_kernel() {
    __shared__ float s[3*TILE];
    int ch = blockIdx.z;
    int y0 = blockIdx.x * BY;
    int z0 = blockIdx.y * BZ;
    int tid = threadIdx.x;

    const float* la = g_la + (size_t)ch * PVOL;
    const float* pr = g_pr + (size_t)ch * PVOL;

    for (int i = tid; i < TILE; i += 64) {
        int x = i % RXP;
        int t = i / RXP;
        int y = t % RY;
        int z = t / RY;
        int gy = y0 + y, gz = z0 + z;
        float va = 0.f, vb = 0.f;
        if (x < PD && gy < PD && gz < PD) {
            int gi = (gz*PD + gy)*PD + x;
            va = la[gi];
            vb = pr[gi];
        }
        s[i]          = va;
        s[TILE + i]   = vb;
        s[2*TILE + i] = 1.f;
    }
    __syncthreads();

    int ty = tid >> 3, tx = tid & 7;
    int rdel[8], cdel[8];
    #pragma unroll
    for (int i = 0; i < 8; i++) {
        rdel[i] = delta_of(ty*8 + i);
        cdel[i] = delta_of(tx*8 + i);
    }

    float acc[8][8];
    #pragma unroll
    for (int i = 0; i < 8; i++)
        #pragma unroll
        for (int j = 0; j < 8; j++) acc[i][j] = 0.f;

    int yC = min(BY, ND - y0);
    int zC = min(BZ, ND - z0);

    for (int zb = 0; zb < zC; zb++) {
        for (int yb = 0; yb < yC; yb++) {
            int kb = (zb*RY + yb) * RXP;
            #pragma unroll 2
            for (int xb = 0; xb < ND; xb++) {
                int k = kb + xb;
                float a[8], b[8];
                #pragma unroll
                for (int i = 0; i < 8; i++) a[i] = s[rdel[i] + k];
                #pragma unroll
                for (int j = 0; j < 8; j++) b[j] = s[cdel[j] + k];
                #pragma unroll
                for (int i = 0; i < 8; i++)
                    #pragma unroll
                    for (int j = 0; j < 8; j++)
                        acc[i][j] = fmaf(a[i], b[j], acc[i][j]);
            }
        }
    }

    double* G = g_gram + (size_t)ch * GSZ * GSZ;
    #pragma unroll
    for (int i = 0; i < 8; i++) {
        int r = ty*8 + i;
        if (r > 54) continue;
        #pragma unroll
        for (int j = 0; j < 8; j++) {
            int c = tx*8 + j;
            if (c > 54) continue;
            atomicAdd(&G[r*GSZ + c], (double)acc[i][j]);
        }
    }
}

// ---------------------------------------------------------------------------
// Parallel Cholesky (lower), 27x27 fp64, in shared memory. One sqrt+div per
// step on thread 0; rank-1 update spread across the block. invd[k] = 1/L[k][k].
__device__ void chol27p(double* A, double* invd, int tid) {
    for (int k = 0; k < 27; k++) {
        if (tid == 0) {
            double sv = sqrt(A[k*27 + k]);
            A[k*27 + k] = sv;
            invd[k] = 1.0 / sv;
        }
        __syncthreads();
        double iv = invd[k];
        for (int i = k + 1 + tid; i < 27; i += FT) A[i*27 + k] *= iv;
        __syncthreads();
        for (int e = tid; e < 27*27; e += FT) {
            int i = e / 27, j = e % 27;
            if (j > k && j <= i)
                A[e] -= A[i*27 + k] * A[j*27 + k];
        }
        __syncthreads();
    }
}

__global__ __launch_bounds__(FT) void finalize_kernel(float* out) {
    __shared__ double Cla[27*27], P[27*27], T[27*27];
    __shared__ double invd[27];
    __shared__ double red;
    int ch = blockIdx.x;
    int tid = threadIdx.x;
    const double* G = g_gram + (size_t)ch * GSZ * GSZ;
    const double M = (double)(ND*ND*ND);   // 97336
    const double ALPHA = 0.0005;

    if (tid == 0) red = 0.0;

    // mean-corrected covariances. T starts as la_pr_cov^T laid out [i_pr][m_la]:
    // T[i*27+m] = cov(la_m, pr_i) so that forward-substituting Lp into rows of T
    // yields T = Lp^{-1} la_pr^T directly.
    for (int e = tid; e < 27*27; e += FT) {
        int i = e / 27, j = e % 27;
        double Sli = G[i*GSZ + 54];          // sum la_i
        double Spi = G[(27+i)*GSZ + 54];     // sum pr_i
        double Slj = G[j*GSZ + 54];
        double Spj = G[(27+j)*GSZ + 54];
        Cla[e]        = G[i*GSZ + j]           - Sli*Slj / M;
        P[e]          = G[(27+i)*GSZ + (27+j)] - Spi*Spj / M + (i == j ? ALPHA : 0.0);
        T[i*27 + j]   = G[j*GSZ + (27+i)]      - Slj*Spi / M;   // cov(la_j, pr_i)
    }
    __syncthreads();

    chol27p(P, invd, tid);   // P = Lp

    // Step-parallel forward substitution: T <- Lp^{-1} T  (27 RHS columns)
    for (int k = 0; k < 27; k++) {
        // scale row k
        for (int m = tid; m < 27; m += FT) T[k*27 + m] *= invd[k];
        __syncthreads();
        // eliminate below
        for (int e = tid; e < (26 - k) * 27; e += FT) {
            int i = k + 1 + e / 27;
            int m = e % 27;
            T[i*27 + m] -= P[i*27 + k] * T[k*27 + m];
        }
        __syncthreads();
    }

    // appro = la_cov - T^T T + aI   (into P)
    for (int e = tid; e < 27*27; e += FT) {
        int i = e / 27, j = e % 27;
        double v = Cla[e];
        #pragma unroll 9
        for (int k = 0; k < 27; k++) v -= T[k*27 + i] * T[k*27 + j];
        P[e] = v + (i == j ? ALPHA : 0.0);
    }
    __syncthreads();

    chol27p(P, invd, tid);

    if (tid < 27) {
        double v = log(P[tid*27 + tid] + 1e-8);
        atomicAdd(&red, v);
    }
    __syncthreads();
    if (tid == 0) {
        // sum_c mean_n rmi / 27  ==  sum_ch rmi_ch / 54
        atomicAdd(out, (float)(red / 54.0));
    }
}

// ---------------------------------------------------------------------------
extern "C" void kernel_launch(void* const* d_in, const int* in_sizes, int n_in,
                              void* d_out, int out_size) {
    const float* logits = (const float*)d_in[0];
    const int*   labels = (const int*)d_in[1];
    float* out = (float*)d_out;

    zero_kernel<<<(NCH*GSZ*GSZ + 255)/256, 256>>>(out);
    pool_kernel<<<(NCH*PVOL + 255)/256, 256>>>(logits, labels);
    dim3 g((ND + BY - 1)/BY, (ND + BZ - 1)/BZ, NCH);   // (8, 8, 8)
    gram_kernel<<<g, 64>>>();
    finalize_kernel<<<NCH, FT>>>(out);
}

// round 5
// speedup vs baseline: 1.4124x; 1.0385x over previous
#include <cuda_runtime.h>
#include <math.h>

#define NCH 8            // 2 batches x 4 classes
#define GD 96            // input spatial dim
#define PD 48            // pooled dim
#define PVOL (PD*PD*PD)  // 110592
#define ND 46            // base-voxel dim (48 - 2)
#define HALF_D 27
#define GSZ 64           // padded gram size (54 data rows + ones row at 54)

#define BY 6
#define BZ 6
#define RXP 50           // padded raw tile x-extent
#define RY 8             // BY + 2
#define RZ 8             // BZ + 2
#define TILE (RZ*RY*RXP) // 3200 floats per sub-tile

#define FT 128           // finalize threads

static __device__ float  g_la[NCH*PVOL];
static __device__ float  g_pr[NCH*PVOL];
static __device__ double g_gram[NCH*GSZ*GSZ];

// packed f32x2 helpers -------------------------------------------------------
#define PACK2(out, lo, hi) \
    asm("mov.b64 %0, {%1, %2};" : "=l"(out) : "r"(lo), "r"(hi))
#define UNPACK2(lo, hi, in) \
    asm("mov.b64 {%0, %1}, %2;" : "=r"(lo), "=r"(hi) : "l"(in))
#define FMA_F32X2(d, a, b) \
    asm("fma.rn.f32x2 %0, %1, %2, %0;" : "+l"(d) : "l"(a), "l"(b))

// ---------------------------------------------------------------------------
__global__ void zero_kernel(float* out) {
    int i = blockIdx.x * blockDim.x + threadIdx.x;
    if (i < NCH*GSZ*GSZ) g_gram[i] = 0.0;
    if (i == 0) out[0] = 0.0f;
}

// ---------------------------------------------------------------------------
__global__ void pool_kernel(const float* __restrict__ logits,
                            const int* __restrict__ labels) {
    int idx = blockIdx.x * blockDim.x + threadIdx.x;
    if (idx >= NCH*PVOL) return;
    int ch  = idx / PVOL;
    int rem = idx - ch * PVOL;
    int p0 = rem / (PD*PD);
    int p1 = (rem / PD) % PD;
    int p2 = rem % PD;
    int n = ch >> 2;
    int c = ch & 3;

    const float* lg = logits + (size_t)ch * GD*GD*GD;
    const int*   lb = labels + (size_t)n  * GD*GD*GD;

    float la = 0.f, pr = 0.f;
    #pragma unroll
    for (int d0 = 0; d0 < 2; d0++) {
        #pragma unroll
        for (int d1 = 0; d1 < 2; d1++) {
            int base = ((2*p0 + d0) * GD + (2*p1 + d1)) * GD + 2*p2;
            float2 lv = *reinterpret_cast<const float2*>(lg + base);
            int2   bv = *reinterpret_cast<const int2*>(lb + base);
            {
                bool m = (bv.x < 4);
                if (m && bv.x == c) la = 1.f;
                float s = 1.f / (1.f + expf(-lv.x));
                float p = (m ? s : 0.f) + 1e-6f;
                pr = fmaxf(pr, p);
            }
            {
                bool m = (bv.y < 4);
                if (m && bv.y == c) la = 1.f;
                float s = 1.f / (1.f + expf(-lv.y));
                float p = (m ? s : 0.f) + 1e-6f;
                pr = fmaxf(pr, p);
            }
        }
    }
    g_la[idx] = la;
    g_pr[idx] = pr;
}

// ---------------------------------------------------------------------------
__device__ __forceinline__ int delta_of(int r) {
    if (r < 27)  return ((r/9)*RY + (r/3)%3) * RXP + (r%3);
    if (r < 54) { int q = r - 27; return TILE + ((q/9)*RY + (q/3)%3) * RXP + (q%3); }
    return 2*TILE;
}

__global__ __launch_bounds__(64) void gram_kernel() {
    __shared__ float s[3*TILE];
    int ch = blockIdx.z;
    int y0 = blockIdx.x * BY;
    int z0 = blockIdx.y * BZ;
    int tid = threadIdx.x;

    const float* la = g_la + (size_t)ch * PVOL;
    const float* pr = g_pr + (size_t)ch * PVOL;

    for (int i = tid; i < TILE; i += 64) {
        int x = i % RXP;
        int t = i / RXP;
        int y = t % RY;
        int z = t / RY;
        int gy = y0 + y, gz = z0 + z;
        float va = 0.f, vb = 0.f;
        if (x < PD && gy < PD && gz < PD) {
            int gi = (gz*PD + gy)*PD + x;
            va = la[gi];
            vb = pr[gi];
        }
        s[i]          = va;
        s[TILE + i]   = vb;
        s[2*TILE + i] = 1.f;
    }
    __syncthreads();

    int ty = tid >> 3, tx = tid & 7;
    int rdel[8], cdel[8];
    #pragma unroll
    for (int i = 0; i < 8; i++) {
        rdel[i] = delta_of(ty*8 + i);
        cdel[i] = delta_of(tx*8 + i);
    }

    unsigned long long acc2[8][4];
    #pragma unroll
    for (int i = 0; i < 8; i++)
        #pragma unroll
        for (int j = 0; j < 4; j++) acc2[i][j] = 0ULL;

    int yC = min(BY, ND - y0);
    int zC = min(BZ, ND - z0);

    for (int zb = 0; zb < zC; zb++) {
        for (int yb = 0; yb < yC; yb++) {
            int kb = (zb*RY + yb) * RXP;
            #pragma unroll 2
            for (int xb = 0; xb < ND; xb++) {
                int k = kb + xb;
                float a[8], b[8];
                #pragma unroll
                for (int i = 0; i < 8; i++) a[i] = s[rdel[i] + k];
                #pragma unroll
                for (int j = 0; j < 8; j++) b[j] = s[cdel[j] + k];
                unsigned long long b2[4];
                #pragma unroll
                for (int j = 0; j < 4; j++)
                    PACK2(b2[j], __float_as_uint(b[2*j]), __float_as_uint(b[2*j+1]));
                #pragma unroll
                for (int i = 0; i < 8; i++) {
                    unsigned long long a2;
                    PACK2(a2, __float_as_uint(a[i]), __float_as_uint(a[i]));
                    #pragma unroll
                    for (int j = 0; j < 4; j++)
                        FMA_F32X2(acc2[i][j], a2, b2[j]);
                }
            }
        }
    }

    // flush lower triangle (r >= c) only; Gram is symmetric and all needed
    // blocks (la-la, pr-pr, pr-la cross, ones row 54) live there.
    double* G = g_gram + (size_t)ch * GSZ * GSZ;
    #pragma unroll
    for (int i = 0; i < 8; i++) {
        int r = ty*8 + i;
        if (r > 54) continue;
        #pragma unroll
        for (int j = 0; j < 4; j++) {
            unsigned int lo, hi;
            UNPACK2(lo, hi, acc2[i][j]);
            int c0 = tx*8 + 2*j;
            if (c0 <= r)
                atomicAdd(&G[r*GSZ + c0], (double)__uint_as_float(lo));
            if (c0 + 1 <= r)
                atomicAdd(&G[r*GSZ + c0 + 1], (double)__uint_as_float(hi));
        }
    }
}

// ---------------------------------------------------------------------------
// Finalize, LDL^T formulation: no column scaling, no fp64 sqrt/div chains.
// P (working): strictly-lower holds unscaled v_ik, diag holds pivots D_k.
// Unit-lower L1[i][k] = v_ik / D_k applied on the fly via invD.
__device__ void ldl27(double* A, double* invD, int tid) {
    for (int k = 0; k < 27; k++) {
        if (tid == 0) invD[k] = 1.0 / A[k*27 + k];
        __syncthreads();
        double iv = invD[k];
        for (int e = tid; e < 27*27; e += FT) {
            int i = e / 27, j = e % 27;
            if (j > k && j <= i)
                A[e] -= A[i*27 + k] * A[j*27 + k] * iv;
        }
        __syncthreads();
    }
}

__device__ __forceinline__ double G2(const double* G, int a, int b) {
    return (a >= b) ? G[a*GSZ + b] : G[b*GSZ + a];
}

__global__ __launch_bounds__(FT) void finalize_kernel(float* out) {
    __shared__ double Cla[27*27], P[27*27], U[27*27];
    __shared__ double invD[27];
    __shared__ double red;
    int ch = blockIdx.x;
    int tid = threadIdx.x;
    const double* G = g_gram + (size_t)ch * GSZ * GSZ;
    const double M = (double)(ND*ND*ND);   // 97336
    const double ALPHA = 0.0005;

    if (tid == 0) red = 0.0;

    // mean-corrected covariances (symmetric reads from lower-triangle Gram).
    // U[i][m] = cov(la_m, pr_i)  (rows indexed by pr) -> forward-solve target.
    for (int e = tid; e < 27*27; e += FT) {
        int i = e / 27, j = e % 27;
        double Sli = G[54*GSZ + i];
        double Slj = G[54*GSZ + j];
        double Spi = G[54*GSZ + 27 + i];
        double Spj = G[54*GSZ + 27 + j];
        Cla[e] = G2(G, i, j)           - Sli*Slj / M;
        P[e]   = G2(G, 27+i, 27+j)     - Spi*Spj / M + (i == j ? ALPHA : 0.0);
        U[e]   = G[(27+i)*GSZ + j]     - Slj*Spi / M;   // (27+i) > j: lower
    }
    __syncthreads();

    ldl27(P, invD, tid);   // P = L1 * D * L1^T (unscaled form)

    // U <- L1^{-1} U : unit-lower solve, one barrier per step, no divisions
    for (int k = 0; k < 27; k++) {
        double iv = invD[k];
        for (int e = tid; e < (26 - k) * 27; e += FT) {
            int i = k + 1 + e / 27;
            int m = e % 27;
            U[i*27 + m] -= P[i*27 + k] * iv * U[k*27 + m];
        }
        __syncthreads();
    }

    // appro (lower triangle only) = la_cov - U^T D^{-1} U + aI   -> into P
    for (int e = tid; e < 27*27; e += FT) {
        int i = e / 27, j = e % 27;
        if (j > i) continue;
        double v = Cla[e];
        #pragma unroll 9
        for (int k = 0; k < 27; k++)
            v -= invD[k] * U[k*27 + i] * U[k*27 + j];
        P[e] = v + (i == j ? ALPHA : 0.0);
    }
    __syncthreads();

    ldl27(P, invD, tid);   // diag of P now holds D2_k;  chol diag = sqrt(D2_k)

    if (tid < 27) {
        double v = log(sqrt(P[tid*27 + tid]) + 1e-8);
        atomicAdd(&red, v);
    }
    __syncthreads();
    if (tid == 0) {
        // sum_c mean_n rmi / 27  ==  sum_ch rmi_ch / 54
        atomicAdd(out, (float)(red / 54.0));
    }
}

// ---------------------------------------------------------------------------
extern "C" void kernel_launch(void* const* d_in, const int* in_sizes, int n_in,
                              void* d_out, int out_size) {
    const float* logits = (const float*)d_in[0];
    const int*   labels = (const int*)d_in[1];
    float* out = (float*)d_out;

    zero_kernel<<<(NCH*GSZ*GSZ + 255)/256, 256>>>(out);
    pool_kernel<<<(NCH*PVOL + 255)/256, 256>>>(logits, labels);
    dim3 g((ND + BY - 1)/BY, (ND + BZ - 1)/BZ, NCH);   // (8, 8, 8)
    gram_kernel<<<g, 64>>>();
    finalize_kernel<<<NCH, FT>>>(out);
}